// round 6
// baseline (speedup 1.0000x reference)
#include <cuda_runtime.h>

#define NB 4
#define NT 4096
#define DE 1024
#define DH 64
#define BT (NB*NT)   // 16384 rows

typedef unsigned long long ull;

// Scratch for projected Q, K, V (4 MB each)
__device__ float g_Q[(size_t)BT * DH];
__device__ float g_K[(size_t)BT * DH];
__device__ float g_V[(size_t)BT * DH];

__device__ __forceinline__ float ex2(float x) {
    float y;
    asm("ex2.approx.ftz.f32 %0, %1;" : "=f"(y) : "f"(x));
    return y;
}
__device__ __forceinline__ ull fma2(ull a, ull b, ull c) {
    ull d;
    asm("fma.rn.f32x2 %0, %1, %2, %3;" : "=l"(d) : "l"(a), "l"(b), "l"(c));
    return d;
}
__device__ __forceinline__ ull mul2(ull a, ull b) {
    ull d;
    asm("mul.rn.f32x2 %0, %1, %2;" : "=l"(d) : "l"(a), "l"(b));
    return d;
}
__device__ __forceinline__ ull pack2(float lo, float hi) {
    ull d;
    asm("mov.b64 %0, {%1, %2};" : "=l"(d) : "f"(lo), "f"(hi));
    return d;
}
__device__ __forceinline__ void unpack2(ull v, float& lo, float& hi) {
    asm("mov.b64 {%0, %1}, %2;" : "=f"(lo), "=f"(hi) : "l"(v));
}

// ===================== Kernel 1: QKV projection =====================
// out[row, h] = sum_e x[row, e] * W[h, e]
// M=16384, N=64 (per W), K=1024. Tile: BM=128, BN=64, BK=32; 256 threads.
// Per-thread 8x4 outputs held as 4x4 f32x2 (row pairs packed in lanes).
__global__ __launch_bounds__(256) void qkv_kernel(
    const float* __restrict__ x,
    const float* __restrict__ Wk,
    const float* __restrict__ Wq,
    const float* __restrict__ Wv)
{
    __shared__ float Xs[32][132];  // [k][row], padded (row base 16B-aligned: 132*4=528=33*16)
    __shared__ float Ws[32][68];   // [k][col], padded (272=17*16)

    const float* __restrict__ W;
    float* out;
    const int sel = blockIdx.y;
    if (sel == 0)      { W = Wq; out = g_Q; }
    else if (sel == 1) { W = Wk; out = g_K; }
    else               { W = Wv; out = g_V; }

    const int tid = threadIdx.x;
    const int tx = tid & 15;        // 0..15 -> 4 cols each
    const int ty = tid >> 4;        // 0..15 -> 8 rows each
    const int rowBase = blockIdx.x * 128;

    ull acc2[4][4];   // [row-pair][col], f32x2 lanes = (even row, odd row)
#pragma unroll
    for (int p = 0; p < 4; p++)
#pragma unroll
        for (int j = 0; j < 4; j++) acc2[p][j] = 0ull;

    for (int kc = 0; kc < DE; kc += 32) {
        // Load X tile (128x32) transposed into Xs[k][row]
#pragma unroll
        for (int i = 0; i < 4; i++) {
            int idx4 = tid + i * 256;          // 0..1023 float4s
            int row = idx4 >> 3;               // 0..127
            int kq  = idx4 & 7;                // 0..7
            float4 v = *(const float4*)(x + (size_t)(rowBase + row) * DE + kc + kq * 4);
            Xs[kq*4+0][row] = v.x;
            Xs[kq*4+1][row] = v.y;
            Xs[kq*4+2][row] = v.z;
            Xs[kq*4+3][row] = v.w;
        }
        // Load W tile (64x32) transposed into Ws[k][col]
#pragma unroll
        for (int i = 0; i < 2; i++) {
            int idx4 = tid + i * 256;          // 0..511
            int wrow = idx4 >> 3;              // 0..63
            int kq   = idx4 & 7;
            float4 v = *(const float4*)(W + (size_t)wrow * DE + kc + kq * 4);
            Ws[kq*4+0][wrow] = v.x;
            Ws[kq*4+1][wrow] = v.y;
            Ws[kq*4+2][wrow] = v.z;
            Ws[kq*4+3][wrow] = v.w;
        }
        __syncthreads();
#pragma unroll 8
        for (int k = 0; k < 32; k++) {
            ulonglong2 a01 = *(const ulonglong2*)&Xs[k][ty*8];
            ulonglong2 a23 = *(const ulonglong2*)&Xs[k][ty*8+4];
            ull a2[4] = {a01.x, a01.y, a23.x, a23.y};
            float4 bv = *(const float4*)&Ws[k][tx*4];
            ull b2[4] = {pack2(bv.x, bv.x), pack2(bv.y, bv.y),
                         pack2(bv.z, bv.z), pack2(bv.w, bv.w)};
#pragma unroll
            for (int p = 0; p < 4; p++) {
                acc2[p][0] = fma2(a2[p], b2[0], acc2[p][0]);
                acc2[p][1] = fma2(a2[p], b2[1], acc2[p][1]);
                acc2[p][2] = fma2(a2[p], b2[2], acc2[p][2]);
                acc2[p][3] = fma2(a2[p], b2[3], acc2[p][3]);
            }
        }
        __syncthreads();
    }
#pragma unroll
    for (int p = 0; p < 4; p++) {
        float e[4], o[4];
#pragma unroll
        for (int j = 0; j < 4; j++) unpack2(acc2[p][j], e[j], o[j]);
        *(float4*)(out + (size_t)(rowBase + ty*8 + 2*p)     * DH + tx*4) =
            make_float4(e[0], e[1], e[2], e[3]);
        *(float4*)(out + (size_t)(rowBase + ty*8 + 2*p + 1) * DH + tx*4) =
            make_float4(o[0], o[1], o[2], o[3]);
    }
}

// ===================== Kernel 2: causal flash attention =====================
// BQ = BKV = 64, 512 threads (16 warps). Per-thread: 1 q-row (ty=tid>>3),
// 8 contiguous S/O columns (tx=tid&7), packed as 4 f32x2.
// Row = 8 consecutive lanes -> width-8 shuffle reductions.
// smem = Qs + Xb(K then P) + Vs = exactly 48KB static.
// Each block handles q-tiles (x) and (63-x): 65 KV-tiles total -> perfect balance.
#define SCL (0.125f * 1.4426950408889634f)   // 1/sqrt(64) * log2(e)

__global__ __launch_bounds__(512) void attn_kernel(float* __restrict__ out)
{
    __shared__ float Qs[64*64];  // [h][i] transposed
    __shared__ float Xb[64*64];  // K as [h][j], then P as [i][j]
    __shared__ float Vs[64*64];  // [t][h] natural

    const int tid = threadIdx.x;
    const int tx = tid & 7;    // 8 cols of 8
    const int ty = tid >> 3;   // q-row within tile, 0..63
    const size_t bb = (size_t)blockIdx.y * NT;

#pragma unroll 1
    for (int pass = 0; pass < 2; pass++) {
        const int qt = (pass == 0) ? (int)blockIdx.x : 63 - (int)blockIdx.x;
        const int qbase = qt * 64;

        // Load Q tile transposed, pre-scaled by 1/sqrt(d)*log2e
#pragma unroll
        for (int i = 0; i < 2; i++) {
            int idx4 = tid + i * 512;   // 0..1023
            int r  = idx4 >> 4;         // 0..63 token
            int hq = idx4 & 15;         // float4 within head dim
            float4 v = *(const float4*)(g_Q + (bb + qbase + r) * DH + hq * 4);
            Qs[(hq*4+0)*64 + r] = v.x * SCL;
            Qs[(hq*4+1)*64 + r] = v.y * SCL;
            Qs[(hq*4+2)*64 + r] = v.z * SCL;
            Qs[(hq*4+3)*64 + r] = v.w * SCL;
        }

        float m = -1e30f, l = 0.f;
        ull o2[4] = {0ull, 0ull, 0ull, 0ull};

        for (int kt = 0; kt <= qt; kt++) {
            const int kbase = kt * 64;
            // Load K (transposed into Xb) and V (natural into Vs)
#pragma unroll
            for (int i = 0; i < 2; i++) {
                int idx4 = tid + i * 512;
                int r  = idx4 >> 4;
                int hq = idx4 & 15;
                float4 v = *(const float4*)(g_K + (bb + kbase + r) * DH + hq * 4);
                Xb[(hq*4+0)*64 + r] = v.x;
                Xb[(hq*4+1)*64 + r] = v.y;
                Xb[(hq*4+2)*64 + r] = v.z;
                Xb[(hq*4+3)*64 + r] = v.w;
                float4 w = *(const float4*)(g_V + (bb + kbase + r) * DH + hq * 4);
                *(float4*)&Vs[r*64 + hq*4] = w;
            }
            __syncthreads();   // tiles (and Qs on first iter) visible

            // S row-slice: s2[j2] lanes = cols (tx*8+2*j2, tx*8+2*j2+1)
            ull s2[4] = {0ull, 0ull, 0ull, 0ull};
#pragma unroll 16
            for (int h = 0; h < 64; h++) {
                float q = Qs[h*64 + ty];
                ull q2 = pack2(q, q);
                ulonglong2 k01 = *(const ulonglong2*)&Xb[h*64 + tx*8];
                ulonglong2 k23 = *(const ulonglong2*)&Xb[h*64 + tx*8 + 4];
                s2[0] = fma2(q2, k01.x, s2[0]);
                s2[1] = fma2(q2, k01.y, s2[1]);
                s2[2] = fma2(q2, k23.x, s2[2]);
                s2[3] = fma2(q2, k23.y, s2[3]);
            }

            float s[8];
#pragma unroll
            for (int j = 0; j < 4; j++) unpack2(s2[j], s[2*j], s[2*j+1]);

            // Causal mask (diagonal tile only): col tx*8+jl must be <= row ty
            if (kt == qt) {
#pragma unroll
                for (int jl = 0; jl < 8; jl++)
                    if (tx*8 + jl > ty) s[jl] = -1e30f;
            }

            // Online softmax over this row slice (row = 8 lanes, width-8 shfl)
            float tmax = s[0];
#pragma unroll
            for (int jl = 1; jl < 8; jl++) tmax = fmaxf(tmax, s[jl]);
#pragma unroll
            for (int w = 1; w < 8; w <<= 1)
                tmax = fmaxf(tmax, __shfl_xor_sync(0xffffffffu, tmax, w, 8));
            float mn = fmaxf(m, tmax);
            float corr = ex2(m - mn);
            m = mn;
            float rs = 0.f;
#pragma unroll
            for (int jl = 0; jl < 8; jl++) {
                float p = ex2(s[jl] - mn);
                s[jl] = p;
                rs += p;
            }
#pragma unroll
            for (int w = 1; w < 8; w <<= 1)
                rs += __shfl_xor_sync(0xffffffffu, rs, w, 8);
            l = l * corr + rs;
            ull corr2 = pack2(corr, corr);
#pragma unroll
            for (int d = 0; d < 4; d++) o2[d] = mul2(o2[d], corr2);

            __syncthreads();  // all threads done reading Xb as K

            // Write P row-slice into Xb[i][j]
            *(float4*)&Xb[ty*64 + tx*8]     = make_float4(s[0], s[1], s[2], s[3]);
            *(float4*)&Xb[ty*64 + tx*8 + 4] = make_float4(s[4], s[5], s[6], s[7]);
            __syncthreads();  // P visible

            // O += P @ V   (o2[d2] lanes = head dims (tx*8+2*d2, +1))
#pragma unroll 16
            for (int kv = 0; kv < 64; kv++) {
                float p = Xb[ty*64 + kv];
                ull p2 = pack2(p, p);
                ulonglong2 v01 = *(const ulonglong2*)&Vs[kv*64 + tx*8];
                ulonglong2 v23 = *(const ulonglong2*)&Vs[kv*64 + tx*8 + 4];
                o2[0] = fma2(p2, v01.x, o2[0]);
                o2[1] = fma2(p2, v01.y, o2[1]);
                o2[2] = fma2(p2, v23.x, o2[2]);
                o2[3] = fma2(p2, v23.y, o2[3]);
            }
            __syncthreads();  // done with Xb/Vs before next tile load
        }

        // Epilogue: normalize and store this row slice
        float inv = 1.f / l;
        float o[8];
#pragma unroll
        for (int d = 0; d < 4; d++) unpack2(o2[d], o[2*d], o[2*d+1]);
        *(float4*)(out + (bb + qbase + ty) * DH + tx*8) =
            make_float4(o[0]*inv, o[1]*inv, o[2]*inv, o[3]*inv);
        *(float4*)(out + (bb + qbase + ty) * DH + tx*8 + 4) =
            make_float4(o[4]*inv, o[5]*inv, o[6]*inv, o[7]*inv);
    }
}

extern "C" void kernel_launch(void* const* d_in, const int* in_sizes, int n_in,
                              void* d_out, int out_size) {
    const float* x  = (const float*)d_in[0];
    const float* Wk = (const float*)d_in[1];
    const float* Wq = (const float*)d_in[2];
    const float* Wv = (const float*)d_in[3];
    float* out = (float*)d_out;

    qkv_kernel<<<dim3(BT/128, 3), 256>>>(x, Wk, Wq, Wv);
    attn_kernel<<<dim3(32, NB), 512>>>(out);

    (void)in_sizes; (void)n_in; (void)out_size;
}

// round 8
// speedup vs baseline: 2.5466x; 2.5466x over previous
#include <cuda_runtime.h>

#define NB 4
#define NT 4096
#define DE 1024
#define DH 64
#define BT (NB*NT)   // 16384 rows
#define NSL 4        // KV slices per q-tile

typedef unsigned long long ull;

// Scratch: projected Q,K,V (4MB each) + split-KV partials (16MB + 512KB)
__device__ float g_Q[(size_t)BT * DH];
__device__ float g_K[(size_t)BT * DH];
__device__ float g_V[(size_t)BT * DH];
__device__ float g_Op[(size_t)NSL * BT * DH];  // unnormalized partial O
__device__ float g_m[(size_t)NSL * BT];        // running max (log2 domain)
__device__ float g_l[(size_t)NSL * BT];        // running denom

__device__ __forceinline__ float ex2(float x) {
    float y;
    asm("ex2.approx.ftz.f32 %0, %1;" : "=f"(y) : "f"(x));
    return y;
}
__device__ __forceinline__ ull fma2(ull a, ull b, ull c) {
    ull d;
    asm("fma.rn.f32x2 %0, %1, %2, %3;" : "=l"(d) : "l"(a), "l"(b), "l"(c));
    return d;
}
__device__ __forceinline__ ull pack2(float lo, float hi) {
    ull d;
    asm("mov.b64 %0, {%1, %2};" : "=l"(d) : "f"(lo), "f"(hi));
    return d;
}
__device__ __forceinline__ void unpack2(ull v, float& lo, float& hi) {
    asm("mov.b64 {%0, %1}, %2;" : "=f"(lo), "=f"(hi) : "l"(v));
}

// ===================== Kernel 1: QKV projection (f32x2) =====================
// out[row, h] = sum_e x[row, e] * W[h, e]
// M=16384, N=64 (per W), K=1024. Tile: BM=128, BN=64, BK=32; 256 threads.
// Per-thread 8x4 outputs held as 4x4 f32x2 (row pairs packed in lanes).
__global__ __launch_bounds__(256) void qkv_kernel(
    const float* __restrict__ x,
    const float* __restrict__ Wk,
    const float* __restrict__ Wq,
    const float* __restrict__ Wv)
{
    __shared__ float Xs[32][132];  // [k][row], padded (row base 16B-aligned)
    __shared__ float Ws[32][68];   // [k][col], padded

    const float* __restrict__ W;
    float* out;
    const int sel = blockIdx.y;
    if (sel == 0)      { W = Wq; out = g_Q; }
    else if (sel == 1) { W = Wk; out = g_K; }
    else               { W = Wv; out = g_V; }

    const int tid = threadIdx.x;
    const int tx = tid & 15;        // 0..15 -> 4 cols each
    const int ty = tid >> 4;        // 0..15 -> 8 rows each
    const int rowBase = blockIdx.x * 128;

    ull acc2[4][4];   // [row-pair][col], lanes = (even row, odd row)
#pragma unroll
    for (int p = 0; p < 4; p++)
#pragma unroll
        for (int j = 0; j < 4; j++) acc2[p][j] = 0ull;

    for (int kc = 0; kc < DE; kc += 32) {
#pragma unroll
        for (int i = 0; i < 4; i++) {
            int idx4 = tid + i * 256;          // 0..1023 float4s
            int row = idx4 >> 3;               // 0..127
            int kq  = idx4 & 7;                // 0..7
            float4 v = *(const float4*)(x + (size_t)(rowBase + row) * DE + kc + kq * 4);
            Xs[kq*4+0][row] = v.x;
            Xs[kq*4+1][row] = v.y;
            Xs[kq*4+2][row] = v.z;
            Xs[kq*4+3][row] = v.w;
        }
#pragma unroll
        for (int i = 0; i < 2; i++) {
            int idx4 = tid + i * 256;          // 0..511
            int wrow = idx4 >> 3;              // 0..63
            int kq   = idx4 & 7;
            float4 v = *(const float4*)(W + (size_t)wrow * DE + kc + kq * 4);
            Ws[kq*4+0][wrow] = v.x;
            Ws[kq*4+1][wrow] = v.y;
            Ws[kq*4+2][wrow] = v.z;
            Ws[kq*4+3][wrow] = v.w;
        }
        __syncthreads();
#pragma unroll 8
        for (int k = 0; k < 32; k++) {
            ulonglong2 a01 = *(const ulonglong2*)&Xs[k][ty*8];
            ulonglong2 a23 = *(const ulonglong2*)&Xs[k][ty*8+4];
            ull a2[4] = {a01.x, a01.y, a23.x, a23.y};
            float4 bv = *(const float4*)&Ws[k][tx*4];
            ull b2[4] = {pack2(bv.x, bv.x), pack2(bv.y, bv.y),
                         pack2(bv.z, bv.z), pack2(bv.w, bv.w)};
#pragma unroll
            for (int p = 0; p < 4; p++) {
                acc2[p][0] = fma2(a2[p], b2[0], acc2[p][0]);
                acc2[p][1] = fma2(a2[p], b2[1], acc2[p][1]);
                acc2[p][2] = fma2(a2[p], b2[2], acc2[p][2]);
                acc2[p][3] = fma2(a2[p], b2[3], acc2[p][3]);
            }
        }
        __syncthreads();
    }
#pragma unroll
    for (int p = 0; p < 4; p++) {
        float e[4], o[4];
#pragma unroll
        for (int j = 0; j < 4; j++) unpack2(acc2[p][j], e[j], o[j]);
        *(float4*)(out + (size_t)(rowBase + ty*8 + 2*p)     * DH + tx*4) =
            make_float4(e[0], e[1], e[2], e[3]);
        *(float4*)(out + (size_t)(rowBase + ty*8 + 2*p + 1) * DH + tx*4) =
            make_float4(o[0], o[1], o[2], o[3]);
    }
}

// ===================== Kernel 2: split-KV causal flash attention =====================
// EXACT R2-verified inner structure: BQ=BKV=64, 256 threads (16x16), 4x4 tiles,
// smem 48KB static. Work partition: grid = (64 q-tiles, 4 batches, 4 KV-slices).
// Each CTA processes kv tiles [kv0, kv1) of its q-tile and writes unnormalized
// partials (O', m, l); combine_kernel merges the 4 slices.
#define SCL (0.125f * 1.4426950408889634f)   // 1/sqrt(64) * log2(e)

__global__ __launch_bounds__(256) void attn_partial()
{
    __shared__ float Qs[64*64];  // [h][i] transposed
    __shared__ float Xb[64*64];  // K as [h][j], then P as [i][j]
    __shared__ float Vs[64*64];  // [t][h] natural

    const int tid = threadIdx.x;
    const int tx = tid & 15;   // j / d groups of 4
    const int ty = tid >> 4;   // i groups of 4
    const int qt = blockIdx.x;            // 0..63
    const size_t bb = (size_t)blockIdx.y * NT;
    const int sl = blockIdx.z;            // 0..3
    const int qbase = qt * 64;

    const int nkv = qt + 1;
    const int len = (nkv + NSL - 1) / NSL;
    const int kv0 = sl * len;
    const int kv1 = (kv0 + len < nkv) ? (kv0 + len) : nkv;

    float o[4][4], m[4], l[4];
#pragma unroll
    for (int i = 0; i < 4; i++) {
        m[i] = -1e30f; l[i] = 0.f;
#pragma unroll
        for (int j = 0; j < 4; j++) o[i][j] = 0.f;
    }

    const size_t pbase = (size_t)sl * BT + bb + qbase;

    if (kv0 < kv1) {
        // Load Q tile transposed, pre-scaled by 1/sqrt(d)*log2e
#pragma unroll
        for (int i = 0; i < 4; i++) {
            int idx4 = tid + i * 256;
            int r  = idx4 >> 4;     // 0..63 token
            int hq = idx4 & 15;     // float4 within head dim
            float4 v = *(const float4*)(g_Q + (bb + qbase + r) * DH + hq * 4);
            Qs[(hq*4+0)*64 + r] = v.x * SCL;
            Qs[(hq*4+1)*64 + r] = v.y * SCL;
            Qs[(hq*4+2)*64 + r] = v.z * SCL;
            Qs[(hq*4+3)*64 + r] = v.w * SCL;
        }

        for (int kt = kv0; kt < kv1; kt++) {
            const int kbase = kt * 64;
            // Load K (transposed into Xb) and V (natural into Vs)
#pragma unroll
            for (int i = 0; i < 4; i++) {
                int idx4 = tid + i * 256;
                int r  = idx4 >> 4;
                int hq = idx4 & 15;
                float4 v = *(const float4*)(g_K + (bb + kbase + r) * DH + hq * 4);
                Xb[(hq*4+0)*64 + r] = v.x;
                Xb[(hq*4+1)*64 + r] = v.y;
                Xb[(hq*4+2)*64 + r] = v.z;
                Xb[(hq*4+3)*64 + r] = v.w;
                float4 w = *(const float4*)(g_V + (bb + kbase + r) * DH + hq * 4);
                *(float4*)&Vs[r*64 + hq*4] = w;
            }
            __syncthreads();   // tiles (and Qs on first iter) visible

            // S tile: s[ii][jj] = sum_h Qs[h][4ty+ii] * K[h][4tx+jj]
            float s[4][4];
#pragma unroll
            for (int ii = 0; ii < 4; ii++)
#pragma unroll
                for (int jj = 0; jj < 4; jj++) s[ii][jj] = 0.f;
#pragma unroll 8
            for (int h = 0; h < 64; h++) {
                float4 qa = *(const float4*)&Qs[h*64 + ty*4];
                float4 kb = *(const float4*)&Xb[h*64 + tx*4];
                float a[4] = {qa.x, qa.y, qa.z, qa.w};
#pragma unroll
                for (int ii = 0; ii < 4; ii++) {
                    s[ii][0] = fmaf(a[ii], kb.x, s[ii][0]);
                    s[ii][1] = fmaf(a[ii], kb.y, s[ii][1]);
                    s[ii][2] = fmaf(a[ii], kb.z, s[ii][2]);
                    s[ii][3] = fmaf(a[ii], kb.w, s[ii][3]);
                }
            }

            // Causal mask (only on the diagonal tile)
            if (kt == qt) {
#pragma unroll
                for (int ii = 0; ii < 4; ii++)
#pragma unroll
                    for (int jj = 0; jj < 4; jj++)
                        if (tx*4 + jj > ty*4 + ii) s[ii][jj] = -1e30f;
            }

            __syncthreads();  // all threads done reading Xb as K

            // Online softmax; write P into Xb[i][j]
#pragma unroll
            for (int ii = 0; ii < 4; ii++) {
                float tmax = fmaxf(fmaxf(s[ii][0], s[ii][1]), fmaxf(s[ii][2], s[ii][3]));
#pragma unroll
                for (int w = 1; w < 16; w <<= 1)
                    tmax = fmaxf(tmax, __shfl_xor_sync(0xffffffffu, tmax, w));
                float mn = fmaxf(m[ii], tmax);
                float corr = ex2(m[ii] - mn);
                m[ii] = mn;
                float rs = 0.f;
#pragma unroll
                for (int jj = 0; jj < 4; jj++) {
                    float p = ex2(s[ii][jj] - mn);
                    s[ii][jj] = p;
                    rs += p;
                }
#pragma unroll
                for (int w = 1; w < 16; w <<= 1)
                    rs += __shfl_xor_sync(0xffffffffu, rs, w);
                l[ii] = l[ii] * corr + rs;
#pragma unroll
                for (int dd = 0; dd < 4; dd++) o[ii][dd] *= corr;
                *(float4*)&Xb[(ty*4+ii)*64 + tx*4] =
                    make_float4(s[ii][0], s[ii][1], s[ii][2], s[ii][3]);
            }
            __syncthreads();  // P visible

            // O += P @ V
#pragma unroll 8
            for (int kv = 0; kv < 64; kv++) {
                float4 vv = *(const float4*)&Vs[kv*64 + tx*4];
                float pa[4];
#pragma unroll
                for (int ii = 0; ii < 4; ii++) pa[ii] = Xb[(ty*4+ii)*64 + kv];
#pragma unroll
                for (int ii = 0; ii < 4; ii++) {
                    o[ii][0] = fmaf(pa[ii], vv.x, o[ii][0]);
                    o[ii][1] = fmaf(pa[ii], vv.y, o[ii][1]);
                    o[ii][2] = fmaf(pa[ii], vv.z, o[ii][2]);
                    o[ii][3] = fmaf(pa[ii], vv.w, o[ii][3]);
                }
            }
            __syncthreads();  // done with Xb/Vs before next tile load
        }
    }

    // Epilogue: write UNNORMALIZED partials + (m, l) per row
#pragma unroll
    for (int ii = 0; ii < 4; ii++) {
        int r = ty*4 + ii;
        *(float4*)(g_Op + (pbase + r) * DH + tx*4) =
            make_float4(o[ii][0], o[ii][1], o[ii][2], o[ii][3]);
        if (tx == 0) {
            g_m[pbase + r] = m[ii];
            g_l[pbase + r] = l[ii];
        }
    }
}

// ===================== Kernel 3: split-softmax combine =====================
// One thread per (row, float4-chunk): 16384 * 16 threads.
__global__ __launch_bounds__(256) void combine_kernel(float* __restrict__ out)
{
    int idx = blockIdx.x * 256 + threadIdx.x;   // 0 .. BT*16-1
    int r  = idx >> 4;
    int c4 = idx & 15;

    float m0 = g_m[r], m1 = g_m[BT + r], m2 = g_m[2*BT + r], m3 = g_m[3*BT + r];
    float M = fmaxf(fmaxf(m0, m1), fmaxf(m2, m3));
    float w0 = ex2(m0 - M), w1 = ex2(m1 - M), w2 = ex2(m2 - M), w3 = ex2(m3 - M);
    float L = g_l[r]*w0 + g_l[BT + r]*w1 + g_l[2*BT + r]*w2 + g_l[3*BT + r]*w3;
    float inv = 1.f / L;

    size_t off = (size_t)r * DH + c4 * 4;
    float4 a0 = *(const float4*)(g_Op + off);
    float4 a1 = *(const float4*)(g_Op + (size_t)BT*DH   + off);
    float4 a2 = *(const float4*)(g_Op + (size_t)2*BT*DH + off);
    float4 a3 = *(const float4*)(g_Op + (size_t)3*BT*DH + off);

    float4 res;
    res.x = (a0.x*w0 + a1.x*w1 + a2.x*w2 + a3.x*w3) * inv;
    res.y = (a0.y*w0 + a1.y*w1 + a2.y*w2 + a3.y*w3) * inv;
    res.z = (a0.z*w0 + a1.z*w1 + a2.z*w2 + a3.z*w3) * inv;
    res.w = (a0.w*w0 + a1.w*w1 + a2.w*w2 + a3.w*w3) * inv;
    *(float4*)(out + off) = res;
}

extern "C" void kernel_launch(void* const* d_in, const int* in_sizes, int n_in,
                              void* d_out, int out_size) {
    const float* x  = (const float*)d_in[0];
    const float* Wk = (const float*)d_in[1];
    const float* Wq = (const float*)d_in[2];
    const float* Wv = (const float*)d_in[3];
    float* out = (float*)d_out;

    qkv_kernel<<<dim3(BT/128, 3), 256>>>(x, Wk, Wq, Wv);
    attn_partial<<<dim3(64, NB, NSL), 256>>>();
    combine_kernel<<<(BT*16)/256, 256>>>(out);

    (void)in_sizes; (void)n_in; (void)out_size;
}